// round 4
// baseline (speedup 1.0000x reference)
#include <cuda_runtime.h>
#include <cstdint>

typedef unsigned long long ull;

// ---------------- problem constants ----------------
constexpr int BB = 16;
constexpr int N0 = 8192;
constexpr int P1 = 512;
constexpr int P2 = 128;
constexpr int KNN = 16;
constexpr int C1 = 128;
constexpr int C2 = 256;

// ---------------- packed f32x2 helpers ----------------
__device__ __forceinline__ ull pk2(float lo, float hi) {
    ull r; asm("mov.b64 %0, {%1,%2};" : "=l"(r) : "f"(lo), "f"(hi)); return r;
}
__device__ __forceinline__ void upk2(ull v, float& lo, float& hi) {
    asm("mov.b64 {%0,%1}, %2;" : "=f"(lo), "=f"(hi) : "l"(v));
}
__device__ __forceinline__ ull add2(ull a, ull b) {
    ull d; asm("add.rn.f32x2 %0, %1, %2;" : "=l"(d) : "l"(a), "l"(b)); return d;
}
__device__ __forceinline__ ull mul2(ull a, ull b) {
    ull d; asm("mul.rn.f32x2 %0, %1, %2;" : "=l"(d) : "l"(a), "l"(b)); return d;
}
__device__ __forceinline__ ull fma2(ull a, ull b, ull c) {
    ull d; asm("fma.rn.f32x2 %0, %1, %2, %3;" : "=l"(d) : "l"(a), "l"(b), "l"(c)); return d;
}

// ---------------- scratch arena ----------------
constexpr int OFF_L1XYZ = 0;                              // (B,3,P1)
constexpr int OFF_L1PTS = OFF_L1XYZ + BB * 3 * P1;        // (B,P1,C1)
constexpr int OFF_L2XYZ = OFF_L1PTS + BB * P1 * C1;       // (B,3,P2)
constexpr int OFF_L2PTS = OFF_L2XYZ + BB * 3 * P2;        // (B,P2,C2)
constexpr int OFF_W1AT  = OFF_L2PTS + BB * P2 * C2;       // Ipad=8,  O=64
constexpr int OFF_W1BT  = OFF_W1AT + 8 * 64;              // I=64,    O=128
constexpr int OFF_W2AT  = OFF_W1BT + 64 * 128;            // Ipad=132,O=128
constexpr int OFF_W2BT  = OFF_W2AT + 132 * 128;           // I=128,   O=256
constexpr int OFF_W3AT  = OFF_W2BT + 128 * 256;           // Ipad=260,O=512
constexpr int OFF_W3BT  = OFF_W3AT + 260 * 512;           // I=512,   O=256
constexpr int F_TOTAL   = OFF_W3BT + 512 * 256;

constexpr int OFF_FPS1 = 0;
constexpr int OFF_KNN1 = OFF_FPS1 + BB * P1;
constexpr int OFF_FPS2 = OFF_KNN1 + BB * P1 * KNN;
constexpr int OFF_KNN2 = OFF_FPS2 + BB * P2;
constexpr int I_TOTAL  = OFF_KNN2 + BB * P2 * KNN;

__device__ float g_f[F_TOTAL];
__device__ int   g_i[I_TOTAL];

// ---------------- weight prep: W(O,Isrc) -> pair-interleaved WP ----------------
__global__ void prep_weights(const float* __restrict__ W1a, const float* __restrict__ W1b,
                             const float* __restrict__ W2a, const float* __restrict__ W2b,
                             const float* __restrict__ W3a, const float* __restrict__ W3b) {
    int idx = blockIdx.x * blockDim.x + threadIdx.x;
    if (idx < 512) {
        int i2 = idx >> 7, rem = idx & 127, o = rem >> 1, h = rem & 1, i = 2 * i2 + h;
        g_f[OFF_W1AT + idx] = (i < 6) ? W1a[o * 6 + i] : 0.f; return;
    }
    idx -= 512;
    if (idx < 8192) {
        int i2 = idx >> 8, rem = idx & 255, o = rem >> 1, h = rem & 1, i = 2 * i2 + h;
        g_f[OFF_W1BT + idx] = W1b[o * 64 + i]; return;
    }
    idx -= 8192;
    if (idx < 16896) {
        int i2 = idx >> 8, rem = idx & 255, o = rem >> 1, h = rem & 1, i = 2 * i2 + h;
        g_f[OFF_W2AT + idx] = (i < 131) ? W2a[o * 131 + i] : 0.f; return;
    }
    idx -= 16896;
    if (idx < 32768) {
        int i2 = idx >> 9, rem = idx & 511, o = rem >> 1, h = rem & 1, i = 2 * i2 + h;
        g_f[OFF_W2BT + idx] = W2b[o * 128 + i]; return;
    }
    idx -= 32768;
    if (idx < 133120) {
        int i2 = idx >> 10, rem = idx & 1023, o = rem >> 1, h = rem & 1, i = 2 * i2 + h;
        g_f[OFF_W3AT + idx] = (i < 259) ? W3a[o * 259 + i] : 0.f; return;
    }
    idx -= 133120;
    if (idx < 131072) {
        int i2 = idx >> 9, rem = idx & 511, o = rem >> 1, h = rem & 1, i = 2 * i2 + h;
        g_f[OFF_W3BT + idx] = W3b[o * 512 + i]; return;
    }
}

// ---------------- farthest point sampling ----------------
// Scan math UNCHANGED (bit-identical trajectory to verified version).
// Reduction reworked: single barrier per iteration via double-buffered smem,
// stage-2 done redundantly by every warp (all compute identical argmax).
template <int N, int NPOINT, int THREADS, int XYZ_OFF, int IDX_OFF>
__global__ void __launch_bounds__(THREADS) fps_kernel(const float* __restrict__ xyz_in) {
    static_assert(N % (2 * THREADS) == 0, "packing requires even PPT");
    constexpr int PH = N / THREADS / 2;
    constexpr int NW = THREADS / 32;
    const float* xyz;
    if constexpr (XYZ_OFF >= 0) xyz = g_f + XYZ_OFF; else xyz = xyz_in;

    int b = blockIdx.x, t = threadIdx.x;
    int lane = t & 31, w = t >> 5;
    const float* xb = xyz + (size_t)b * 3 * N;

    ull px2[PH], py2[PH], pz2[PH];
    float dd[2 * PH];
#pragma unroll
    for (int k = 0; k < PH; k++) {
        int p0 = t + (2 * k) * THREADS, p1 = t + (2 * k + 1) * THREADS;
        px2[k] = pk2(xb[p0], xb[p1]);
        py2[k] = pk2(xb[N + p0], xb[N + p1]);
        pz2[k] = pk2(xb[2 * N + p0], xb[2 * N + p1]);
        dd[2 * k] = 1e10f; dd[2 * k + 1] = 1e10f;
    }

    __shared__ float sv[2][NW];
    __shared__ int   si[2][NW];

    int far = 0;
    int* ob = g_i + IDX_OFF + b * NPOINT;

    for (int j = 0; j < NPOINT; j++) {
        if (t == 0) ob[j] = far;
        float cx = __ldg(xb + far);
        float cy = __ldg(xb + N + far);
        float cz = __ldg(xb + 2 * N + far);
        ull ncx2 = pk2(-cx, -cx), ncy2 = pk2(-cy, -cy), ncz2 = pk2(-cz, -cz);

        float best = -1e30f; int bidx = 0x7fffffff;
#pragma unroll
        for (int k = 0; k < PH; k++) {
            ull dx2 = add2(px2[k], ncx2);
            ull dy2 = add2(py2[k], ncy2);
            ull dz2 = add2(pz2[k], ncz2);
            ull s2 = add2(add2(mul2(dx2, dx2), mul2(dy2, dy2)), mul2(dz2, dz2));
            float d0, d1; upk2(s2, d0, d1);
            float nd0 = fminf(dd[2 * k], d0);     dd[2 * k] = nd0;
            if (nd0 > best) { best = nd0; bidx = t + (2 * k) * THREADS; }
            float nd1 = fminf(dd[2 * k + 1], d1); dd[2 * k + 1] = nd1;
            if (nd1 > best) { best = nd1; bidx = t + (2 * k + 1) * THREADS; }
        }
#pragma unroll
        for (int off = 16; off; off >>= 1) {
            float ov = __shfl_down_sync(0xffffffffu, best, off);
            int   oi = __shfl_down_sync(0xffffffffu, bidx, off);
            if (ov > best || (ov == best && oi < bidx)) { best = ov; bidx = oi; }
        }
        int par = j & 1;
        if (lane == 0) { sv[par][w] = best; si[par][w] = bidx; }
        __syncthreads();
        // stage 2: every warp redundantly reduces the NW partials
        float v = (lane < NW) ? sv[par][lane] : -1e30f;
        int  ix = (lane < NW) ? si[par][lane] : 0x7fffffff;
#pragma unroll
        for (int off = 16; off; off >>= 1) {
            float ov = __shfl_down_sync(0xffffffffu, v, off);
            int   oi = __shfl_down_sync(0xffffffffu, ix, off);
            if (ov > v || (ov == v && oi < ix)) { v = ov; ix = oi; }
        }
        far = __shfl_sync(0xffffffffu, ix, 0);
    }
}

// ---------------- gather sampled xyz ----------------
template <int NSRC, int PDST, int SRC_OFF, int IDX_OFF, int DST_OFF>
__global__ void gather_kernel(const float* __restrict__ src_in) {
    const float* src;
    if constexpr (SRC_OFF >= 0) src = g_f + SRC_OFF; else src = src_in;
    int b = blockIdx.x;
    for (int p = threadIdx.x; p < PDST; p += blockDim.x) {
        int j = g_i[IDX_OFF + b * PDST + p];
#pragma unroll
        for (int c = 0; c < 3; c++)
            g_f[DST_OFF + (b * 3 + c) * PDST + p] = src[((size_t)b * 3 + c) * NSRC + j];
    }
}

// ---------------- kNN: f32x2 distances, float4(x,y,z,r2) smem tiles ----------------
__device__ __forceinline__ ull pack_key(float d, int i) {
    unsigned b = __float_as_uint(d);
    b = (b & 0x80000000u) ? ~b : (b | 0x80000000u);
    return ((ull)b << 32) | (unsigned)i;
}

// verified warp-distributed sorted top-16 insert primitive (unchanged semantics)
#define KNN_INSERT(KEY)                                                        \
    do {                                                                       \
        ull _thr = __shfl_sync(0xffffffffu, mykey, 15);                        \
        ull _up  = __shfl_up_sync(0xffffffffu, mykey, 1);                      \
        if ((KEY) < _thr && lane < 16 && mykey > (KEY))                        \
            mykey = (lane > 0 && _up > (KEY)) ? _up : (KEY);                   \
    } while (0)

template <int P, int N, int TILE, int CENT_OFF, int PTS_OFF, int OUT_OFF>
__global__ void __launch_bounds__(256) knn_kernel(const float* __restrict__ pts_in) {
    __shared__ float4 s4[TILE];
    const float* cent = g_f + CENT_OFF;
    const float* pts;
    if constexpr (PTS_OFF >= 0) pts = g_f + PTS_OFF; else pts = pts_in;

    int b = blockIdx.x / (P / 8);
    int p = (blockIdx.x % (P / 8)) * 8 + (threadIdx.x >> 5);
    int lane = threadIdx.x & 31;

    const float* cb = cent + b * 3 * P;
    const float* pb = pts + (size_t)b * 3 * N;
    float cx = cb[p], cy = cb[P + p], cz = cb[2 * P + p];
    float c2 = cx * cx + cy * cy + cz * cz;
    ull CX2 = pk2(cx, cx), CY2 = pk2(cy, cy), CZ2 = pk2(cz, cz);
    ull C22 = pk2(c2, c2), NEG2 = pk2(-2.f, -2.f);

    ull mykey = 0xFF800000FFFFFFFFull;              // pack(+inf, ~0)
    float thrf = __int_as_float(0x7f800000);        // +inf

    for (int t0 = 0; t0 < N; t0 += TILE) {
        __syncthreads();
        for (int i = threadIdx.x; i < TILE; i += 256) {
            float x = pb[t0 + i], y = pb[N + t0 + i], z = pb[2 * N + t0 + i];
            s4[i] = make_float4(x, y, z, x * x + y * y + z * z);
        }
        __syncthreads();
        for (int c0 = 0; c0 < TILE; c0 += 64) {
            float4 a = s4[c0 + 2 * lane];
            float4 e = s4[c0 + 2 * lane + 1];
            ull T = mul2(pk2(a.x, e.x), CX2);
            T = fma2(pk2(a.y, e.y), CY2, T);
            T = fma2(pk2(a.z, e.z), CZ2, T);
            ull D = fma2(T, NEG2, add2(pk2(a.w, e.w), C22));
            float d0, d1; upk2(D, d0, d1);
            unsigned m = __ballot_sync(0xffffffffu, fminf(d0, d1) <= thrf);
            if (m) {
                int ibase = t0 + c0;
                while (m) {
                    int src = __ffs(m) - 1;
                    m &= m - 1;
                    float e0 = __shfl_sync(0xffffffffu, d0, src);
                    float e1 = __shfl_sync(0xffffffffu, d1, src);
                    ull K0 = pack_key(e0, ibase + 2 * src);
                    KNN_INSERT(K0);
                    ull K1 = pack_key(e1, ibase + 2 * src + 1);
                    KNN_INSERT(K1);
                }
                ull k15 = __shfl_sync(0xffffffffu, mykey, 15);
                unsigned hb = (unsigned)(k15 >> 32);
                unsigned obits = (hb & 0x80000000u) ? (hb & 0x7fffffffu) : ~hb;
                thrf = __uint_as_float(obits);
            }
        }
    }
    if (lane < 16)
        g_i[OUT_OFF + ((b * P + p) << 4) + lane] = (int)(mykey & 0xffffffffu);
}

// ---------------- SA1: group + MLP(6->64 relu ->128) + maxpool ----------------
__global__ void __launch_bounds__(128) sa1_kernel(const float* __restrict__ xyz,
                                                  const float* __restrict__ b1a,
                                                  const float* __restrict__ b1b) {
    __shared__ alignas(16) float feat[16 * 8];
    __shared__ alignas(16) float hid[16 * 64];
    int t = threadIdx.x;
    int cid = blockIdx.x;
    int b = cid >> 9, p = cid & 511;

    if (t < 16) {
        int j = g_i[OFF_KNN1 + (cid << 4) + t];
        const float* xb = xyz + (size_t)b * 3 * N0;
        float vx = xb[j], vy = xb[N0 + j], vz = xb[2 * N0 + j];
        const float* cxb = g_f + OFF_L1XYZ + b * 3 * P1;
        feat[t * 8 + 0] = vx - cxb[p];
        feat[t * 8 + 1] = vy - cxb[P1 + p];
        feat[t * 8 + 2] = vz - cxb[2 * P1 + p];
        feat[t * 8 + 3] = vx;
        feat[t * 8 + 4] = vy;
        feat[t * 8 + 5] = vz;
        feat[t * 8 + 6] = 0.f;
        feat[t * 8 + 7] = 0.f;
    }
    __syncthreads();

    if (t < 64) {
        ull acc[16];
#pragma unroll
        for (int n = 0; n < 16; n++) acc[n] = 0ull;
#pragma unroll
        for (int i4 = 0; i4 < 2; i4++) {
            ull wA = *(const ull*)&g_f[OFF_W1AT + ((2 * i4) * 64 + t) * 2];
            ull wB = *(const ull*)&g_f[OFF_W1AT + ((2 * i4 + 1) * 64 + t) * 2];
#pragma unroll
            for (int n = 0; n < 16; n++) {
                ulonglong2 f = *(const ulonglong2*)&feat[n * 8 + 4 * i4];
                acc[n] = fma2(wA, f.x, acc[n]);
                acc[n] = fma2(wB, f.y, acc[n]);
            }
        }
        float bb = b1a[t];
#pragma unroll
        for (int n = 0; n < 16; n++) {
            float e, o; upk2(acc[n], e, o);
            hid[n * 64 + t] = fmaxf(e + o + bb, 0.f);
        }
    }
    __syncthreads();

    {
        ull acc[16];
#pragma unroll
        for (int n = 0; n < 16; n++) acc[n] = 0ull;
#pragma unroll 4
        for (int h4 = 0; h4 < 16; h4++) {
            ull wA = *(const ull*)&g_f[OFF_W1BT + ((2 * h4) * 128 + t) * 2];
            ull wB = *(const ull*)&g_f[OFF_W1BT + ((2 * h4 + 1) * 128 + t) * 2];
#pragma unroll
            for (int n = 0; n < 16; n++) {
                ulonglong2 f = *(const ulonglong2*)&hid[n * 64 + 4 * h4];
                acc[n] = fma2(wA, f.x, acc[n]);
                acc[n] = fma2(wB, f.y, acc[n]);
            }
        }
        float mx = -1e30f;
#pragma unroll
        for (int n = 0; n < 16; n++) {
            float e, o; upk2(acc[n], e, o);
            mx = fmaxf(mx, e + o);
        }
        g_f[OFF_L1PTS + ((size_t)(b * P1 + p)) * C1 + t] = mx + b1b[t];
    }
}

// ---------------- SA2: group + MLP(131->128 relu ->256) + maxpool ----------------
__global__ void __launch_bounds__(128) sa2_kernel(const float* __restrict__ b2a,
                                                  const float* __restrict__ b2b) {
    __shared__ alignas(16) float feat[16 * 132];
    __shared__ alignas(16) float hid[16 * 128];
    __shared__ int sj[16];
    int t = threadIdx.x;
    int cid = blockIdx.x;
    int b = cid >> 7, p = cid & 127;

    if (t < 16) sj[t] = g_i[OFF_KNN2 + (cid << 4) + t];
    __syncthreads();

    for (int idx = t; idx < 16 * 132; idx += 128) {
        int n = idx / 132, c = idx - n * 132;
        int j = sj[n];
        float v;
        if (c < 3)
            v = g_f[OFF_L1XYZ + (b * 3 + c) * P1 + j] - g_f[OFF_L2XYZ + (b * 3 + c) * P2 + p];
        else if (c < 131)
            v = g_f[OFF_L1PTS + ((size_t)(b * P1 + j)) * C1 + (c - 3)];
        else
            v = 0.f;
        feat[idx] = v;
    }
    __syncthreads();

    {
        ull acc[16];
#pragma unroll
        for (int n = 0; n < 16; n++) acc[n] = 0ull;
#pragma unroll 3
        for (int i4 = 0; i4 < 33; i4++) {
            ull wA = *(const ull*)&g_f[OFF_W2AT + ((2 * i4) * 128 + t) * 2];
            ull wB = *(const ull*)&g_f[OFF_W2AT + ((2 * i4 + 1) * 128 + t) * 2];
#pragma unroll
            for (int n = 0; n < 16; n++) {
                ulonglong2 f = *(const ulonglong2*)&feat[n * 132 + 4 * i4];
                acc[n] = fma2(wA, f.x, acc[n]);
                acc[n] = fma2(wB, f.y, acc[n]);
            }
        }
        float bb = b2a[t];
#pragma unroll
        for (int n = 0; n < 16; n++) {
            float e, o; upk2(acc[n], e, o);
            hid[n * 128 + t] = fmaxf(e + o + bb, 0.f);
        }
    }
    __syncthreads();

    // GEMM2: both output channels (t, t+128) fused -> features loaded ONCE
    {
        int o0 = t, o1 = t + 128;
        ull acc0[16], acc1[16];
#pragma unroll
        for (int n = 0; n < 16; n++) { acc0[n] = 0ull; acc1[n] = 0ull; }
#pragma unroll 2
        for (int h4 = 0; h4 < 32; h4++) {
            ull wA0 = *(const ull*)&g_f[OFF_W2BT + ((2 * h4) * 256 + o0) * 2];
            ull wB0 = *(const ull*)&g_f[OFF_W2BT + ((2 * h4 + 1) * 256 + o0) * 2];
            ull wA1 = *(const ull*)&g_f[OFF_W2BT + ((2 * h4) * 256 + o1) * 2];
            ull wB1 = *(const ull*)&g_f[OFF_W2BT + ((2 * h4 + 1) * 256 + o1) * 2];
#pragma unroll
            for (int n = 0; n < 16; n++) {
                ulonglong2 f = *(const ulonglong2*)&hid[n * 128 + 4 * h4];
                acc0[n] = fma2(wA0, f.x, acc0[n]);
                acc0[n] = fma2(wB0, f.y, acc0[n]);
                acc1[n] = fma2(wA1, f.x, acc1[n]);
                acc1[n] = fma2(wB1, f.y, acc1[n]);
            }
        }
        float mx0 = -1e30f, mx1 = -1e30f;
#pragma unroll
        for (int n = 0; n < 16; n++) {
            float e, o; upk2(acc0[n], e, o); mx0 = fmaxf(mx0, e + o);
            upk2(acc1[n], e, o);             mx1 = fmaxf(mx1, e + o);
        }
        size_t base = ((size_t)(b * P2 + p)) * C2;
        g_f[OFF_L2PTS + base + o0] = mx0 + b2b[o0];
        g_f[OFF_L2PTS + base + o1] = mx1 + b2b[o1];
    }
}

// ---------------- SA3: group-all MLP(259->512 relu ->256) + global max ----------------
__device__ __forceinline__ void atomicMaxFloat(float* addr, float v) {
    if (v >= 0.f) atomicMax((int*)addr, __float_as_int(v));
    else          atomicMin((unsigned*)addr, __float_as_uint(v));
}

__global__ void init_out_kernel(float* out, int n) {
    int i = blockIdx.x * blockDim.x + threadIdx.x;
    if (i < n) out[i] = __int_as_float(0xff800000);
}

__global__ void __launch_bounds__(256) sa3_kernel(const float* __restrict__ b3a,
                                                  const float* __restrict__ b3b,
                                                  float* __restrict__ out) {
    __shared__ alignas(16) float feat[8 * 260];
    __shared__ alignas(16) float hid[8 * 512];
    int t = threadIdx.x;
    int b = blockIdx.x >> 4, tile = blockIdx.x & 15;

    for (int idx = t; idx < 8 * 260; idx += 256) {
        int n = idx / 260, c = idx - n * 260;
        int pt = tile * 8 + n;
        float v;
        if (c < 3)        v = g_f[OFF_L2XYZ + (b * 3 + c) * P2 + pt];
        else if (c < 259) v = g_f[OFF_L2PTS + ((size_t)(b * P2 + pt)) * C2 + (c - 3)];
        else              v = 0.f;
        feat[idx] = v;
    }
    __syncthreads();

    // GEMM1: both hidden channels (t, t+256) fused -> features loaded ONCE
    {
        int h0 = t, h1 = t + 256;
        ull acc0[8], acc1[8];
#pragma unroll
        for (int n = 0; n < 8; n++) { acc0[n] = 0ull; acc1[n] = 0ull; }
#pragma unroll 5
        for (int i4 = 0; i4 < 65; i4++) {
            ull wA0 = *(const ull*)&g_f[OFF_W3AT + ((2 * i4) * 512 + h0) * 2];
            ull wB0 = *(const ull*)&g_f[OFF_W3AT + ((2 * i4 + 1) * 512 + h0) * 2];
            ull wA1 = *(const ull*)&g_f[OFF_W3AT + ((2 * i4) * 512 + h1) * 2];
            ull wB1 = *(const ull*)&g_f[OFF_W3AT + ((2 * i4 + 1) * 512 + h1) * 2];
#pragma unroll
            for (int n = 0; n < 8; n++) {
                ulonglong2 f = *(const ulonglong2*)&feat[n * 260 + 4 * i4];
                acc0[n] = fma2(wA0, f.x, acc0[n]);
                acc0[n] = fma2(wB0, f.y, acc0[n]);
                acc1[n] = fma2(wA1, f.x, acc1[n]);
                acc1[n] = fma2(wB1, f.y, acc1[n]);
            }
        }
        float bb0 = b3a[h0], bb1 = b3a[h1];
#pragma unroll
        for (int n = 0; n < 8; n++) {
            float e, o; upk2(acc0[n], e, o);
            hid[n * 512 + h0] = fmaxf(e + o + bb0, 0.f);
            upk2(acc1[n], e, o);
            hid[n * 512 + h1] = fmaxf(e + o + bb1, 0.f);
        }
    }
    __syncthreads();

    {
        ull acc[8];
#pragma unroll
        for (int n = 0; n < 8; n++) acc[n] = 0ull;
#pragma unroll 4
        for (int h4 = 0; h4 < 128; h4++) {
            ull wA = *(const ull*)&g_f[OFF_W3BT + ((2 * h4) * 256 + t) * 2];
            ull wB = *(const ull*)&g_f[OFF_W3BT + ((2 * h4 + 1) * 256 + t) * 2];
#pragma unroll
            for (int n = 0; n < 8; n++) {
                ulonglong2 f = *(const ulonglong2*)&hid[n * 512 + 4 * h4];
                acc[n] = fma2(wA, f.x, acc[n]);
                acc[n] = fma2(wB, f.y, acc[n]);
            }
        }
        float mx = -1e30f;
#pragma unroll
        for (int n = 0; n < 8; n++) {
            float e, o; upk2(acc[n], e, o);
            mx = fmaxf(mx, e + o);
        }
        atomicMaxFloat(out + b * 256 + t, mx + b3b[t]);
    }
}

// ---------------- launch ----------------
extern "C" void kernel_launch(void* const* d_in, const int* in_sizes, int n_in,
                              void* d_out, int out_size) {
    const float* pc  = (const float*)d_in[0];
    const float* W1a = (const float*)d_in[1];
    const float* b1a = (const float*)d_in[2];
    const float* W1b = (const float*)d_in[3];
    const float* b1b = (const float*)d_in[4];
    const float* W2a = (const float*)d_in[5];
    const float* b2a = (const float*)d_in[6];
    const float* W2b = (const float*)d_in[7];
    const float* b2b = (const float*)d_in[8];
    const float* W3a = (const float*)d_in[9];
    const float* b3a = (const float*)d_in[10];
    const float* W3b = (const float*)d_in[11];
    const float* b3b = (const float*)d_in[12];
    float* out = (float*)d_out;

    prep_weights<<<(322560 + 255) / 256, 256>>>(W1a, W1b, W2a, W2b, W3a, W3b);

    // SA1
    fps_kernel<N0, P1, 1024, -1, OFF_FPS1><<<BB, 1024>>>(pc);
    gather_kernel<N0, P1, -1, OFF_FPS1, OFF_L1XYZ><<<BB, 256>>>(pc);
    knn_kernel<P1, N0, 2048, OFF_L1XYZ, -1, OFF_KNN1><<<BB * (P1 / 8), 256>>>(pc);
    sa1_kernel<<<BB * P1, 128>>>(pc, b1a, b1b);

    // SA2
    fps_kernel<P1, P2, 256, OFF_L1XYZ, OFF_FPS2><<<BB, 256>>>(nullptr);
    gather_kernel<P1, P2, OFF_L1XYZ, OFF_FPS2, OFF_L2XYZ><<<BB, 128>>>(nullptr);
    knn_kernel<P2, P1, 512, OFF_L2XYZ, OFF_L1XYZ, OFF_KNN2><<<BB * (P2 / 8), 256>>>(nullptr);
    sa2_kernel<<<BB * P2, 128>>>(b2a, b2b);

    // SA3
    init_out_kernel<<<16, 256>>>(out, BB * 256);
    sa3_kernel<<<BB * 16, 256>>>(b3a, b3b, out);
}